// round 17
// baseline (speedup 1.0000x reference)
#include <cuda_runtime.h>
#include <cuda_fp16.h>
#include <cstdint>

// Mean-shift clustering, 3 iterations, fp16 mma.sync m16n8k16 tensor cores.
// (tcgen05 unavailable: harness builds via compute_103 (non-'a').)
//
//   S = X^T X ; K = exp(6 S) (symmetric) ; colsum[m] = row-sum of K
//   Out[d,m] = (sum_n K[m,n] X[d,n]) / colsum[m]
//
// GEMM1: 128x128 tiles, upper tile pairs only (symmetry). L2-resident
//        operands, measured effective HMMA rt ~9.6 cyc -> untouched.
// GEMM2: A streams the 128MB g_K from DRAM -> was latency-bound (1TB/s
//        achieved, 12% of peak). Now staged via a 3-stage cp.async pipeline
//        (2 chunks in flight) instead of single-chunk register prefetch.
//        colsum read from the staged smem tile (bit-identical values/order).

#define NPTS  8192
#define DFEAT 256
#define DELTA 6.0f
#define KC    32     // GEMM1 chunk (k halves)
#define AST   20     // GEMM1 smem row stride in uint32
#define KC2   64     // GEMM2 chunk (k halves)
#define AST2  36     // GEMM2 smem row stride in uint32 (32 data + 4 pad)
#define STAGES 3
// Dynamic smem layout (uint32 units): A stages at s*2304, B stages at
// 6912 + s*4608. Total 20736 u32 = 82944 bytes.
#define A_ST_U32 (64 * AST2)            // 2304
#define B_ST_U32 (128 * AST2)           // 4608
#define B_BASE   (STAGES * A_ST_U32)    // 6912
#define DSM_BYTES ((B_BASE + STAGES * B_ST_U32) * 4)

__device__ __align__(16) __half g_K [(size_t)NPTS * NPTS];   // 128 MB
__device__ __align__(16) __half g_XT[(size_t)NPTS * DFEAT];  // 4 MB, [n][d]
__device__ __align__(16) __half g_Xh[(size_t)DFEAT * NPTS];  // 4 MB, [d][n]

__device__ __forceinline__ float h2sum(uint32_t u) {
    float2 f = __half22float2(*reinterpret_cast<__half2*>(&u));
    return f.x + f.y;
}
__device__ __forceinline__ uint32_t smem_u32(const void* p) {
    uint32_t a;
    asm("{ .reg .u64 t; cvta.to.shared.u64 t, %1; cvt.u32.u64 %0, t; }"
        : "=r"(a) : "l"(p));
    return a;
}

__device__ __forceinline__ void mma16(float* c, const uint32_t* a, const uint32_t* b) {
    asm volatile(
        "mma.sync.aligned.m16n8k16.row.col.f32.f16.f16.f32 "
        "{%0,%1,%2,%3}, {%4,%5,%6,%7}, {%8,%9}, {%0,%1,%2,%3};"
        : "+f"(c[0]), "+f"(c[1]), "+f"(c[2]), "+f"(c[3])
        : "r"(a[0]), "r"(a[1]), "r"(a[2]), "r"(a[3]), "r"(b[0]), "r"(b[1]));
}

// ---------------------------------------------------------------------------
// Transpose + fp16 convert: g_XT[n][d] = h(X[d][n]); g_Xh[d][n] = h(X[d][n]).
// ---------------------------------------------------------------------------
__global__ void __launch_bounds__(256) ms_transpose(const float* __restrict__ X) {
    __shared__ float t[32][33];
    const int tx = threadIdx.x, ty = threadIdx.y;
    const int n0 = blockIdx.x * 32, d0 = blockIdx.y * 32;
#pragma unroll
    for (int i = 0; i < 32; i += 8) {
        const float v = X[(size_t)(d0 + ty + i) * NPTS + n0 + tx];
        t[ty + i][tx] = v;
        g_Xh[(size_t)(d0 + ty + i) * NPTS + n0 + tx] = __float2half_rn(v);
    }
    __syncthreads();
#pragma unroll
    for (int i = 0; i < 32; i += 8)
        g_XT[(size_t)(n0 + ty + i) * DFEAT + d0 + tx] = __float2half_rn(t[tx][ty + i]);
}

// ---------------------------------------------------------------------------
// GEMM1: g_K = fp16(exp(DELTA * X^T X)), symmetric -> upper tile pairs only.
// (UNCHANGED — measured effective rt ~9.6 cyc.)
// ---------------------------------------------------------------------------
__global__ void __launch_bounds__(256, 2) ms_mma_gemm1() {
    const int bx = blockIdx.x, by = blockIdx.y;
    if (bx < by) return;
    const bool diag = (bx == by);

    __shared__ uint32_t As[128 * AST];
    __shared__ uint32_t Bs[128 * AST];

    const int tid  = threadIdx.x;
    const int n0   = by * 128, m0 = bx * 128;
    const int warp = tid >> 5, lane = tid & 31;
    const int g    = lane >> 2, t = lane & 3;
    const int wm   = (warp & 1) * 64;
    const int wn   = (warp >> 1) * 32;
    const int srow = tid >> 1;
    const int sc   = (tid & 1) * 8;

    float C[16][4];
#pragma unroll
    for (int i = 0; i < 16; ++i)
#pragma unroll
        for (int j = 0; j < 4; ++j) C[i][j] = 0.0f;

    const uint4* gA = reinterpret_cast<const uint4*>(
        g_XT + (size_t)(n0 + srow) * DFEAT) + (tid & 1) * 2;
    const uint4* gB = reinterpret_cast<const uint4*>(
        g_XT + (size_t)(m0 + srow) * DFEAT) + (tid & 1) * 2;

    uint4 pa0 = gA[0], pa1 = gA[1];
    uint4 pb0 = gB[0], pb1 = gB[1];

#pragma unroll 1
    for (int c = 0; c < DFEAT / KC; ++c) {
        __syncthreads();
        *reinterpret_cast<uint4*>(As + srow * AST + sc)     = pa0;
        *reinterpret_cast<uint4*>(As + srow * AST + sc + 4) = pa1;
        *reinterpret_cast<uint4*>(Bs + srow * AST + sc)     = pb0;
        *reinterpret_cast<uint4*>(Bs + srow * AST + sc + 4) = pb1;
        __syncthreads();

        if (c + 1 < DFEAT / KC) {
            const int o = (c + 1) * 4;
            pa0 = gA[o]; pa1 = gA[o + 1];
            pb0 = gB[o]; pb1 = gB[o + 1];
        }

#pragma unroll
        for (int ks = 0; ks < 2; ++ks) {
            uint32_t bf[4][2];
#pragma unroll
            for (int nt = 0; nt < 4; ++nt) {
                const uint32_t* bp = Bs + (wn + nt * 8 + g) * AST + ks * 8 + t;
                bf[nt][0] = bp[0];
                bf[nt][1] = bp[4];
            }
#pragma unroll
            for (int mt = 0; mt < 4; ++mt) {
                const uint32_t* a0p = As + (wm + mt * 16 + g) * AST + ks * 8 + t;
                const uint32_t* a1p = a0p + 8 * AST;
                uint32_t af[4];
                af[0] = a0p[0];
                af[1] = a1p[0];
                af[2] = a0p[4];
                af[3] = a1p[4];
#pragma unroll
                for (int nt = 0; nt < 4; ++nt) mma16(C[mt * 4 + nt], af, bf[nt]);
            }
        }
    }

#pragma unroll
    for (int mt = 0; mt < 4; ++mt) {
#pragma unroll
        for (int nt = 0; nt < 4; ++nt) {
            const float* cc = C[mt * 4 + nt];
            const int i0 = wm + mt * 16 + g;
            const int j0 = wn + nt * 8 + 2 * t;
            const __half h0 = __float2half_rn(__expf(DELTA * cc[0]));
            const __half h1 = __float2half_rn(__expf(DELTA * cc[1]));
            const __half h2 = __float2half_rn(__expf(DELTA * cc[2]));
            const __half h3 = __float2half_rn(__expf(DELTA * cc[3]));

            g_K[(size_t)(m0 + j0)     * NPTS + n0 + i0]     = h0;
            g_K[(size_t)(m0 + j0 + 1) * NPTS + n0 + i0]     = h1;
            g_K[(size_t)(m0 + j0)     * NPTS + n0 + i0 + 8] = h2;
            g_K[(size_t)(m0 + j0 + 1) * NPTS + n0 + i0 + 8] = h3;

            if (!diag) {
                *reinterpret_cast<__half2*>(g_K + (size_t)(n0 + i0)     * NPTS + m0 + j0) =
                    __halves2half2(h0, h1);
                *reinterpret_cast<__half2*>(g_K + (size_t)(n0 + i0 + 8) * NPTS + m0 + j0) =
                    __halves2half2(h2, h3);
            }
        }
    }
}

// ---------------------------------------------------------------------------
// GEMM2: Out[d,m] = (sum_n K[m,n] X[d,n]) / colsum[m]
// Block 64(m) x 128(d), grid (128, 2) = 256 CTAs, 2/SM. KC2 = 64.
// 3-stage cp.async pipeline (2 chunks in flight) hides DRAM latency of the
// g_K stream. colsum read from the staged A tile each phase.
// ---------------------------------------------------------------------------
__global__ void __launch_bounds__(256, 2) ms_mma_gemm2(float* __restrict__ Out) {
    extern __shared__ uint32_t dsm[];
    __shared__ float cs_sm[64];
    const uint32_t sbase = smem_u32(dsm);

    const int tid  = threadIdx.x;
    const int m0   = blockIdx.x * 64, d0 = blockIdx.y * 128;
    const int warp = tid >> 5, lane = tid & 31;
    const int g    = lane >> 2, t = lane & 3;
    const int wm   = (warp & 1) * 32;
    const int wn   = (warp >> 1) * 32;
    const int arow = tid >> 2;            // A row 0..63 (4 thr/row)
    const int ac   = (tid & 3) * 8;       // A col base (uint32 units)
    const int brow = tid >> 1;            // B row 0..127
    const int bc   = (tid & 1) * 16;      // B col base (uint32 units)

    // Global sources for chunk c (advance by c*KC2 halves).
    const __half* gA = g_K  + (size_t)(m0 + arow) * NPTS + (tid & 3) * 16;
    const __half* gB = g_Xh + (size_t)(d0 + brow) * NPTS + (tid & 1) * 32;

    const uint32_t adst0 = sbase + (uint32_t)(arow * AST2 + ac) * 4;
    const uint32_t bdst0 = sbase + (uint32_t)(B_BASE + brow * AST2 + bc) * 4;

    float C[8][4];
#pragma unroll
    for (int i = 0; i < 8; ++i)
#pragma unroll
        for (int j = 0; j < 4; ++j) C[i][j] = 0.0f;
    float csum = 0.0f;

    // Issue one chunk's loads into its ring stage and commit the group.
#define ISSUE_CHUNK(c_)                                                        \
    do {                                                                       \
        const int s_ = (c_) % STAGES;                                          \
        const uint32_t ad_ = adst0 + (uint32_t)(s_ * A_ST_U32) * 4;            \
        const __half* as_ = gA + (size_t)(c_) * KC2;                           \
        asm volatile(                                                          \
            "cp.async.cg.shared.global [%0], [%1], 16;\n\t"                    \
            "cp.async.cg.shared.global [%2], [%3], 16;"                        \
            :: "r"(ad_), "l"(as_), "r"(ad_ + 16), "l"(as_ + 8) : "memory");    \
        const uint32_t bd_ = bdst0 + (uint32_t)(s_ * B_ST_U32) * 4;            \
        const __half* bs_ = gB + (size_t)(c_) * KC2;                           \
        asm volatile(                                                          \
            "cp.async.cg.shared.global [%0], [%1], 16;\n\t"                    \
            "cp.async.cg.shared.global [%2], [%3], 16;\n\t"                    \
            "cp.async.cg.shared.global [%4], [%5], 16;\n\t"                    \
            "cp.async.cg.shared.global [%6], [%7], 16;"                        \
            :: "r"(bd_), "l"(bs_), "r"(bd_ + 16), "l"(bs_ + 8),                \
               "r"(bd_ + 32), "l"(bs_ + 16), "r"(bd_ + 48), "l"(bs_ + 24)      \
            : "memory");                                                       \
        asm volatile("cp.async.commit_group;" ::: "memory");                   \
    } while (0)

    ISSUE_CHUNK(0);
    ISSUE_CHUNK(1);

#pragma unroll 1
    for (int c = 0; c < NPTS / KC2; ++c) {
        asm volatile("cp.async.wait_group 1;" ::: "memory");  // chunk c ready
        __syncthreads();
        // Refill the stage consumed two iterations ago (all threads passed
        // the barrier above, so its last consumers are done).
        if (c + 2 < NPTS / KC2) ISSUE_CHUNK(c + 2);

        const int s = c % STAGES;
        const uint32_t* As = dsm + s * A_ST_U32;
        const uint32_t* Bs = dsm + B_BASE + s * B_ST_U32;

        // colsum partial for row m0+arow: this thread's 16 staged K halves.
        {
            const uint32_t* ap = As + arow * AST2 + ac;
#pragma unroll
            for (int i = 0; i < 8; ++i) csum += h2sum(ap[i]);
        }

#pragma unroll
        for (int ks = 0; ks < 4; ++ks) {
            uint32_t bf[4][2];
#pragma unroll
            for (int nt = 0; nt < 4; ++nt) {
                const uint32_t* bp = Bs + (wn + nt * 8 + g) * AST2 + ks * 8 + t;
                bf[nt][0] = bp[0];
                bf[nt][1] = bp[4];
            }
#pragma unroll
            for (int mt = 0; mt < 2; ++mt) {
                const uint32_t* a0p = As + (wm + mt * 16 + g) * AST2 + ks * 8 + t;
                const uint32_t* a1p = a0p + 8 * AST2;
                uint32_t af[4];
                af[0] = a0p[0];
                af[1] = a1p[0];
                af[2] = a0p[4];
                af[3] = a1p[4];
#pragma unroll
                for (int nt = 0; nt < 4; ++nt) mma16(C[mt * 4 + nt], af, bf[nt]);
            }
        }
    }
#undef ISSUE_CHUNK

    // colsum: reduce the 4 loader threads (consecutive lanes) per row.
    csum += __shfl_xor_sync(0xffffffffu, csum, 1);
    csum += __shfl_xor_sync(0xffffffffu, csum, 2);
    if ((tid & 3) == 0) cs_sm[arow] = csum;
    __syncthreads();

    // Epilogue: Out[d0+j][m0+i] = D[i][j] / colsum[m0+i]
#pragma unroll
    for (int mt = 0; mt < 2; ++mt) {
        const int i0 = wm + mt * 16 + g;
        const float inv0 = 1.0f / cs_sm[i0];
        const float inv1 = 1.0f / cs_sm[i0 + 8];
#pragma unroll
        for (int nt = 0; nt < 4; ++nt) {
            const float* cc = C[mt * 4 + nt];
            const int j0 = wn + nt * 8 + 2 * t;
            float* r0 = Out + (size_t)(d0 + j0) * NPTS + m0 + i0;
            float* r1 = Out + (size_t)(d0 + j0 + 1) * NPTS + m0 + i0;
            r0[0] = cc[0] * inv0;
            r1[0] = cc[1] * inv0;
            r0[8] = cc[2] * inv1;
            r1[8] = cc[3] * inv1;
        }
    }
}

// ---------------------------------------------------------------------------
// Launch: 3 chained iterations; kernel launches only -> graph-capturable.
// (cudaFuncSetAttribute is a host-side config call, not a stream op.)
// ---------------------------------------------------------------------------
extern "C" void kernel_launch(void* const* d_in, const int* in_sizes, int n_in,
                              void* d_out, int out_size) {
    const float* X0 = (const float*)d_in[0];
    float* out = (float*)d_out;

    cudaFuncSetAttribute(ms_mma_gemm2,
                         cudaFuncAttributeMaxDynamicSharedMemorySize, DSM_BYTES);

    const float* cur = X0;
    for (int it = 0; it < 3; ++it) {
        float* O = out + (size_t)it * DFEAT * NPTS;
        ms_transpose<<<dim3(NPTS / 32, DFEAT / 32), dim3(32, 8)>>>(cur);
        ms_mma_gemm1<<<dim3(NPTS / 128, NPTS / 128), 256>>>();
        ms_mma_gemm2<<<dim3(NPTS / 64, 2), 256, DSM_BYTES>>>(O);
        cur = O;
    }
}